// round 14
// baseline (speedup 1.0000x reference)
#include <cuda_runtime.h>
#include <cstdint>

// Problem constants (fixed by reference: POOL=100, N_TASKS=5 -> F_END=20)
#define KEY_D   768
#define EMB_D   768
#define P_FEAT  9216      // EMB_D * HEADS
#define E_P_LEN 8
#define FEND    20
#define TOPKN   10
#define EPSV    1e-12f

// Kernel-1 tiling
#define QPB 8             // queries per block
#define K1_THREADS 640    // 20 warps, warp w <-> key w

// Kernel-2 tiling (R8 tile shape, smem-free)
#define DC  128           // d-chunk per block (4 per lane)
#define QB  64            // queries per block (8 per warp)
#define K2_THREADS 256    // 8 warps

// Transposed dense gate scratch: [FEND][QMAX] (k-major, coalesced consumer)
#define QMAX 4096
__device__ float g_gateT[FEND * QMAX];

// ---------------------------------------------------------------------------
// packed f32x2 helpers
// ---------------------------------------------------------------------------
__device__ __forceinline__ void fma2(unsigned long long& d,
                                     unsigned long long a,
                                     unsigned long long b) {
    asm("fma.rn.f32x2 %0, %1, %2, %0;" : "+l"(d) : "l"(a), "l"(b));
}
__device__ __forceinline__ unsigned long long pack2(float x) {
    unsigned long long r;
    asm("mov.b64 %0, {%1, %1};" : "=l"(r) : "f"(x));
    return r;
}
__device__ __forceinline__ float2 unpack2(unsigned long long v) {
    float2 r;
    asm("mov.b64 {%0, %1}, %2;" : "=f"(r.x), "=f"(r.y) : "l"(v));
    return r;
}

// ---------------------------------------------------------------------------
// Kernel 1 (v14): 8 queries per block, 20 warps (one per key).
// A/K LDGs issued before the staging barrier; per-query dot/na accumulated
// into register arrays, then ALL 16 shfl reduction chains run pipelined
// (independent) instead of 8 serial reduce-per-query rounds.
// ---------------------------------------------------------------------------
__global__ __launch_bounds__(K1_THREADS)
void scores_gate_kernel(const float* __restrict__ x,
                        const float* __restrict__ K,
                        const float* __restrict__ A,
                        int BQ) {
    __shared__ float x_s[QPB][KEY_D];   // 24 KB
    __shared__ float sc[QPB][FEND];

    const int q0  = blockIdx.x * QPB;
    const int tid = threadIdx.x;
    const int w   = tid >> 5;           // key index (0..19)
    const int lane = tid & 31;

    // issue this warp's A/K register loads FIRST (latency overlaps staging)
    float4 a6[6], k6[6];
    {
        const float4* Ar = (const float4*)(A + (size_t)w * KEY_D);
        const float4* Kr = (const float4*)(K + (size_t)w * KEY_D);
#pragma unroll
        for (int i = 0; i < 6; ++i) {
            a6[i] = Ar[lane + 32 * i];
            k6[i] = Kr[lane + 32 * i];
        }
    }

    // stage QPB query rows
    {
        const float4* src = (const float4*)(x + (size_t)q0 * KEY_D);
        for (int i = tid; i < QPB * KEY_D / 4; i += K1_THREADS)
            ((float4*)&x_s[0][0])[i] = src[i];
    }

    // key norm while the barrier forms
    float nk = 0.f;
#pragma unroll
    for (int i = 0; i < 6; ++i) {
        nk = fmaf(k6[i].x, k6[i].x, nk);
        nk = fmaf(k6[i].y, k6[i].y, nk);
        nk = fmaf(k6[i].z, k6[i].z, nk);
        nk = fmaf(k6[i].w, k6[i].w, nk);
    }
#pragma unroll
    for (int off = 16; off; off >>= 1)
        nk += __shfl_xor_sync(0xFFFFFFFFu, nk, off);
    const float nKc = fmaxf(sqrtf(nk), EPSV);

    __syncthreads();

    // accumulate all 8 queries' partials into register arrays
    float dot[QPB], na[QPB];
#pragma unroll
    for (int q = 0; q < QPB; ++q) { dot[q] = 0.f; na[q] = 0.f; }

#pragma unroll
    for (int q = 0; q < QPB; ++q) {
        const float4* xs4 = (const float4*)x_s[q];
#pragma unroll
        for (int i = 0; i < 6; ++i) {
            float4 xa = xs4[lane + 32 * i];
            float t;
            t = xa.x * a6[i].x; dot[q] = fmaf(t, k6[i].x, dot[q]); na[q] = fmaf(t, t, na[q]);
            t = xa.y * a6[i].y; dot[q] = fmaf(t, k6[i].y, dot[q]); na[q] = fmaf(t, t, na[q]);
            t = xa.z * a6[i].z; dot[q] = fmaf(t, k6[i].z, dot[q]); na[q] = fmaf(t, t, na[q]);
            t = xa.w * a6[i].w; dot[q] = fmaf(t, k6[i].w, dot[q]); na[q] = fmaf(t, t, na[q]);
        }
    }

    // 16 independent shfl reduction chains, pipelined per level
#pragma unroll
    for (int off = 16; off; off >>= 1) {
#pragma unroll
        for (int q = 0; q < QPB; ++q) {
            dot[q] += __shfl_xor_sync(0xFFFFFFFFu, dot[q], off);
            na[q]  += __shfl_xor_sync(0xFFFFFFFFu, na[q],  off);
        }
    }
    if (lane == 0) {
#pragma unroll
        for (int q = 0; q < QPB; ++q)
            sc[q][w] = dot[q] / (fmaxf(sqrtf(na[q]), EPSV) * nKc);
    }
    __syncthreads();

    if (tid < QPB && q0 + tid < BQ) {
        float s[FEND];
#pragma unroll
        for (int k = 0; k < FEND; ++k) s[k] = sc[tid][k];
        float tv[TOPKN]; int ti[TOPKN];
#pragma unroll
        for (int j = 0; j < TOPKN; ++j) {
            int bi = 0; float bv = -__int_as_float(0x7F800000); // -inf
#pragma unroll
            for (int k = 0; k < FEND; ++k)
                if (s[k] > bv) { bv = s[k]; bi = k; }
            tv[j] = bv; ti[j] = bi;
            s[bi] = -__int_as_float(0x7F800000);
        }
        float m = tv[0], sum = 0.f;
        float e[TOPKN];
#pragma unroll
        for (int j = 0; j < TOPKN; ++j) { e[j] = __expf(tv[j] - m); sum += e[j]; }
        float inv = 1.f / sum;
        float g[FEND];
#pragma unroll
        for (int k = 0; k < FEND; ++k) g[k] = 0.f;
#pragma unroll
        for (int j = 0; j < TOPKN; ++j) g[ti[j]] = e[j] * inv;
        const int q = q0 + tid;
#pragma unroll
        for (int k = 0; k < FEND; ++k) g_gateT[k * QMAX + q] = g[k];
    }
}

// ---------------------------------------------------------------------------
// Kernel 2 (v14): SMEM-FREE. Same tile as R8 (8 q/warp x 4 d/lane, 4 CTAs),
// but p and gates read directly via L1-cached LDG in the k-loop — no
// staging, no barriers, no shared memory.
// Grid: (P_FEAT/DC, 8, BQ/QB). Block: 256 threads (8 warps).
// Per warp-k: 1 LDG.128 p (lane-distinct, L1/L2-hit) + 2 LDG.128 gates
// (warp-uniform) + 4 pack2 + 16 fma2.
// ---------------------------------------------------------------------------
__global__ __launch_bounds__(K2_THREADS, 4)
void expand_kernel(const float* __restrict__ p,
                   float* __restrict__ out,
                   int BQ) {
    const int d0  = blockIdx.x * DC;
    const int l   = blockIdx.y;
    const int q0  = blockIdx.z * QB;
    const int tid = threadIdx.x;

    const int lane = tid & 31;    // d position within chunk (x4)
    const int w    = tid >> 5;    // query group of 8

    // per-thread source pointers
    const float4* prow =
        (const float4*)(p + (size_t)l * P_FEAT + d0 + lane * 4);
    const size_t pstride = (size_t)E_P_LEN * P_FEAT / 4;   // float4 units per k
    const float* grow = g_gateT + q0 + w * 8;              // + k*QMAX per k

    unsigned long long acc[4][4];
#pragma unroll
    for (int a = 0; a < 4; ++a)
#pragma unroll
        for (int b = 0; b < 4; ++b) acc[a][b] = 0ull;

#pragma unroll 5
    for (int k = 0; k < FEND; ++k) {
        float4 pv = prow[(size_t)k * pstride];
        ulonglong2 ga = *(const ulonglong2*)(grow + (size_t)k * QMAX);     // pairs 0,1
        ulonglong2 gb = *(const ulonglong2*)(grow + (size_t)k * QMAX + 4); // pairs 2,3
        unsigned long long pp0 = pack2(pv.x);
        unsigned long long pp1 = pack2(pv.y);
        unsigned long long pp2 = pack2(pv.z);
        unsigned long long pp3 = pack2(pv.w);
        fma2(acc[0][0], ga.x, pp0); fma2(acc[0][1], ga.x, pp1);
        fma2(acc[0][2], ga.x, pp2); fma2(acc[0][3], ga.x, pp3);
        fma2(acc[1][0], ga.y, pp0); fma2(acc[1][1], ga.y, pp1);
        fma2(acc[1][2], ga.y, pp2); fma2(acc[1][3], ga.y, pp3);
        fma2(acc[2][0], gb.x, pp0); fma2(acc[2][1], gb.x, pp1);
        fma2(acc[2][2], gb.x, pp2); fma2(acc[2][3], gb.x, pp3);
        fma2(acc[3][0], gb.y, pp0); fma2(acc[3][1], gb.y, pp1);
        fma2(acc[3][2], gb.y, pp2); fma2(acc[3][3], gb.y, pp3);
    }

    // writeout: Ek = rows [0, BQ*4), Ev = rows [BQ*4, BQ*8)
    const size_t base = (l < 4) ? 0 : (size_t)BQ * 4;
    const int lrow = l & 3;
    const int dcol = d0 + lane * 4;
#pragma unroll
    for (int qp = 0; qp < 4; ++qp) {
        float2 u0 = unpack2(acc[qp][0]);
        float2 u1 = unpack2(acc[qp][1]);
        float2 u2 = unpack2(acc[qp][2]);
        float2 u3 = unpack2(acc[qp][3]);
        int q = q0 + w * 8 + qp * 2;
        float4 o0 = make_float4(u0.x, u1.x, u2.x, u3.x);
        float4 o1 = make_float4(u0.y, u1.y, u2.y, u3.y);
        if (q < BQ)
            *(float4*)(out + (base + (size_t)q * 4 + lrow) * P_FEAT + dcol) = o0;
        if (q + 1 < BQ)
            *(float4*)(out + (base + (size_t)(q + 1) * 4 + lrow) * P_FEAT + dcol) = o1;
    }
}

// ---------------------------------------------------------------------------
// Launch
// ---------------------------------------------------------------------------
extern "C" void kernel_launch(void* const* d_in, const int* in_sizes, int n_in,
                              void* d_out, int out_size) {
    // Inputs (metadata order): x_querry, l, x_block, K, A, p.
    int iK, iA, ip;
    if (n_in >= 6 && in_sizes[1] == 1) { iK = 3; iA = 4; ip = 5; }
    else                               { iK = 2; iA = 3; ip = 4; }

    const float* x = (const float*)d_in[0];
    const float* K = (const float*)d_in[iK];
    const float* A = (const float*)d_in[iA];
    const float* p = (const float*)d_in[ip];
    float*     out = (float*)d_out;

    const int BQ = in_sizes[0] / KEY_D;   // 1024 for (4, 256)

    scores_gate_kernel<<<(BQ + QPB - 1) / QPB, K1_THREADS>>>(x, K, A, BQ);

    dim3 grid(P_FEAT / DC, E_P_LEN, (BQ + QB - 1) / QB);
    expand_kernel<<<grid, K2_THREADS>>>(p, out, BQ);
}

// round 15
// speedup vs baseline: 1.3901x; 1.3901x over previous
#include <cuda_runtime.h>
#include <cstdint>

// Problem constants (fixed by reference: POOL=100, N_TASKS=5 -> F_END=20)
#define KEY_D   768
#define EMB_D   768
#define P_FEAT  9216      // EMB_D * HEADS
#define E_P_LEN 8
#define FEND    20
#define TOPKN   10
#define EPSV    1e-12f

// Kernel-1 tiling
#define QPB 8             // queries per block
#define K1_THREADS 640    // 20 warps, warp w <-> key w

// Kernel-2 tiling (exact R8/R13)
#define DC  128           // d-chunk per block (4 per lane)
#define QB  64            // queries per block (8 per warp)
#define K2_THREADS 256    // 8 warps

// Transposed dense gate scratch: [FEND][QMAX] (k-major, coalesced consumer)
#define QMAX 4096
__device__ float g_gateT[FEND * QMAX];

// ---------------------------------------------------------------------------
// packed f32x2 helpers
// ---------------------------------------------------------------------------
__device__ __forceinline__ void fma2(unsigned long long& d,
                                     unsigned long long a,
                                     unsigned long long b) {
    asm("fma.rn.f32x2 %0, %1, %2, %0;" : "+l"(d) : "l"(a), "l"(b));
}
__device__ __forceinline__ unsigned long long pack2(float x) {
    unsigned long long r;
    asm("mov.b64 %0, {%1, %1};" : "=l"(r) : "f"(x));
    return r;
}
__device__ __forceinline__ float2 unpack2(unsigned long long v) {
    float2 r;
    asm("mov.b64 {%0, %1}, %2;" : "=f"(r.x), "=f"(r.y) : "l"(v));
    return r;
}

// ---------------------------------------------------------------------------
// Kernel 1 (R13 version + early PDL trigger): 8 queries per block, 20 warps.
// Triggers programmatic launch completion immediately so kernel 2 can begin
// its independent p-staging while this kernel computes gates.
// ---------------------------------------------------------------------------
__global__ __launch_bounds__(K1_THREADS)
void scores_gate_kernel(const float* __restrict__ x,
                        const float* __restrict__ K,
                        const float* __restrict__ A,
                        int BQ) {
    // let the dependent kernel launch right away (its gridsync still waits
    // for THIS grid's full completion before reading g_gateT)
    cudaTriggerProgrammaticLaunchCompletion();

    __shared__ float x_s[QPB][KEY_D];   // 24 KB
    __shared__ float sc[QPB][FEND];

    const int q0  = blockIdx.x * QPB;
    const int tid = threadIdx.x;
    const int w   = tid >> 5;           // key index (0..19)
    const int lane = tid & 31;

    // issue this warp's A/K register loads FIRST (latency overlaps staging)
    float4 a6[6], k6[6];
    {
        const float4* Ar = (const float4*)(A + (size_t)w * KEY_D);
        const float4* Kr = (const float4*)(K + (size_t)w * KEY_D);
#pragma unroll
        for (int i = 0; i < 6; ++i) {
            a6[i] = Ar[lane + 32 * i];
            k6[i] = Kr[lane + 32 * i];
        }
    }

    // stage QPB query rows
    {
        const float4* src = (const float4*)(x + (size_t)q0 * KEY_D);
        for (int i = tid; i < QPB * KEY_D / 4; i += K1_THREADS)
            ((float4*)&x_s[0][0])[i] = src[i];
    }

    // key norm while the barrier forms
    float nk = 0.f;
#pragma unroll
    for (int i = 0; i < 6; ++i) {
        nk = fmaf(k6[i].x, k6[i].x, nk);
        nk = fmaf(k6[i].y, k6[i].y, nk);
        nk = fmaf(k6[i].z, k6[i].z, nk);
        nk = fmaf(k6[i].w, k6[i].w, nk);
    }
#pragma unroll
    for (int off = 16; off; off >>= 1)
        nk += __shfl_xor_sync(0xFFFFFFFFu, nk, off);
    const float nKc = fmaxf(sqrtf(nk), EPSV);

    __syncthreads();

#pragma unroll
    for (int q = 0; q < QPB; ++q) {
        const float4* xs4 = (const float4*)x_s[q];
        float dot = 0.f, na = 0.f;
#pragma unroll
        for (int i = 0; i < 6; ++i) {
            float4 xa = xs4[lane + 32 * i];
            float t;
            t = xa.x * a6[i].x; dot = fmaf(t, k6[i].x, dot); na = fmaf(t, t, na);
            t = xa.y * a6[i].y; dot = fmaf(t, k6[i].y, dot); na = fmaf(t, t, na);
            t = xa.z * a6[i].z; dot = fmaf(t, k6[i].z, dot); na = fmaf(t, t, na);
            t = xa.w * a6[i].w; dot = fmaf(t, k6[i].w, dot); na = fmaf(t, t, na);
        }
#pragma unroll
        for (int off = 16; off; off >>= 1) {
            dot += __shfl_xor_sync(0xFFFFFFFFu, dot, off);
            na  += __shfl_xor_sync(0xFFFFFFFFu, na,  off);
        }
        if (lane == 0)
            sc[q][w] = dot / (fmaxf(sqrtf(na), EPSV) * nKc);
    }
    __syncthreads();

    if (tid < QPB && q0 + tid < BQ) {
        float s[FEND];
#pragma unroll
        for (int k = 0; k < FEND; ++k) s[k] = sc[tid][k];
        float tv[TOPKN]; int ti[TOPKN];
#pragma unroll
        for (int j = 0; j < TOPKN; ++j) {
            int bi = 0; float bv = -__int_as_float(0x7F800000); // -inf
#pragma unroll
            for (int k = 0; k < FEND; ++k)
                if (s[k] > bv) { bv = s[k]; bi = k; }
            tv[j] = bv; ti[j] = bi;
            s[bi] = -__int_as_float(0x7F800000);
        }
        float m = tv[0], sum = 0.f;
        float e[TOPKN];
#pragma unroll
        for (int j = 0; j < TOPKN; ++j) { e[j] = __expf(tv[j] - m); sum += e[j]; }
        float inv = 1.f / sum;
        float g[FEND];
#pragma unroll
        for (int k = 0; k < FEND; ++k) g[k] = 0.f;
#pragma unroll
        for (int j = 0; j < TOPKN; ++j) g[ti[j]] = e[j] * inv;
        const int q = q0 + tid;
#pragma unroll
        for (int k = 0; k < FEND; ++k) g_gateT[k * QMAX + q] = g[k];
    }
}

// ---------------------------------------------------------------------------
// Kernel 2 (exact R8/R13 + PDL gridsync): p staged BEFORE the dependency
// sync (independent of kernel 1), gates staged after.
// Grid: (P_FEAT/DC, 8, BQ/QB). Block: 256 threads (8 warps), 4 CTAs/SM.
// ---------------------------------------------------------------------------
__global__ __launch_bounds__(K2_THREADS, 4)
void expand_kernel(const float* __restrict__ p,
                   float* __restrict__ out,
                   int BQ) {
    __shared__ float ps_s[FEND * DC];   // [k][128]  10 KB
    __shared__ float gt_s[FEND * QB];   // [k][64]    5 KB

    const int d0  = blockIdx.x * DC;
    const int l   = blockIdx.y;
    const int q0  = blockIdx.z * QB;
    const int tid = threadIdx.x;

    // stage p tile (independent of kernel 1's output)
    for (int i = tid; i < FEND * (DC / 4); i += K2_THREADS) {
        int k = i / (DC / 4);
        int c = i % (DC / 4);
        ((float4*)ps_s)[i] =
            *(const float4*)(p + ((size_t)(k * E_P_LEN + l)) * P_FEAT + d0 + c * 4);
    }

    // wait for kernel 1 (gates) to be fully complete + visible
    cudaGridDependencySynchronize();

    // stage gate tile from TRANSPOSED table: linear float4 copy per k-row
    for (int i = tid; i < FEND * (QB / 4); i += K2_THREADS) {
        int k = i / (QB / 4);
        int c = i % (QB / 4);
        ((float4*)gt_s)[i] =
            *(const float4*)(g_gateT + (size_t)k * QMAX + q0 + c * 4);
    }
    __syncthreads();

    const int lane = tid & 31;    // d position within chunk (x4)
    const int w    = tid >> 5;    // query group of 8

    unsigned long long acc[4][4];
#pragma unroll
    for (int a = 0; a < 4; ++a)
#pragma unroll
        for (int b = 0; b < 4; ++b) acc[a][b] = 0ull;

#pragma unroll 5
    for (int k = 0; k < FEND; ++k) {
        float4 pv = ((const float4*)ps_s)[k * (DC / 4) + lane];
        unsigned long long pp0 = pack2(pv.x);
        unsigned long long pp1 = pack2(pv.y);
        unsigned long long pp2 = pack2(pv.z);
        unsigned long long pp3 = pack2(pv.w);
        // 8 gates = 4 query-pairs, uniform per warp
        const ulonglong2* gp = (const ulonglong2*)(gt_s + k * QB + w * 8);
        ulonglong2 ga = gp[0];   // pairs 0,1
        ulonglong2 gb = gp[1];   // pairs 2,3
        fma2(acc[0][0], ga.x, pp0); fma2(acc[0][1], ga.x, pp1);
        fma2(acc[0][2], ga.x, pp2); fma2(acc[0][3], ga.x, pp3);
        fma2(acc[1][0], ga.y, pp0); fma2(acc[1][1], ga.y, pp1);
        fma2(acc[1][2], ga.y, pp2); fma2(acc[1][3], ga.y, pp3);
        fma2(acc[2][0], gb.x, pp0); fma2(acc[2][1], gb.x, pp1);
        fma2(acc[2][2], gb.x, pp2); fma2(acc[2][3], gb.x, pp3);
        fma2(acc[3][0], gb.y, pp0); fma2(acc[3][1], gb.y, pp1);
        fma2(acc[3][2], gb.y, pp2); fma2(acc[3][3], gb.y, pp3);
    }

    // writeout: Ek = rows [0, BQ*4), Ev = rows [BQ*4, BQ*8)
    const size_t base = (l < 4) ? 0 : (size_t)BQ * 4;
    const int lrow = l & 3;
    const int dcol = d0 + lane * 4;
#pragma unroll
    for (int qp = 0; qp < 4; ++qp) {
        float2 u0 = unpack2(acc[qp][0]);
        float2 u1 = unpack2(acc[qp][1]);
        float2 u2 = unpack2(acc[qp][2]);
        float2 u3 = unpack2(acc[qp][3]);
        int q = q0 + w * 8 + qp * 2;
        float4 o0 = make_float4(u0.x, u1.x, u2.x, u3.x);
        float4 o1 = make_float4(u0.y, u1.y, u2.y, u3.y);
        if (q < BQ)
            *(float4*)(out + (base + (size_t)q * 4 + lrow) * P_FEAT + dcol) = o0;
        if (q + 1 < BQ)
            *(float4*)(out + (base + (size_t)(q + 1) * 4 + lrow) * P_FEAT + dcol) = o1;
    }
}

// ---------------------------------------------------------------------------
// Launch: kernel 1 normal, kernel 2 with programmatic dependent launch.
// ---------------------------------------------------------------------------
extern "C" void kernel_launch(void* const* d_in, const int* in_sizes, int n_in,
                              void* d_out, int out_size) {
    // Inputs (metadata order): x_querry, l, x_block, K, A, p.
    int iK, iA, ip;
    if (n_in >= 6 && in_sizes[1] == 1) { iK = 3; iA = 4; ip = 5; }
    else                               { iK = 2; iA = 3; ip = 4; }

    const float* x = (const float*)d_in[0];
    const float* K = (const float*)d_in[iK];
    const float* A = (const float*)d_in[iA];
    const float* p = (const float*)d_in[ip];
    float*     out = (float*)d_out;

    const int BQ = in_sizes[0] / KEY_D;   // 1024 for (4, 256)

    scores_gate_kernel<<<(BQ + QPB - 1) / QPB, K1_THREADS>>>(x, K, A, BQ);

    cudaLaunchConfig_t cfg = {};
    cfg.gridDim  = dim3(P_FEAT / DC, E_P_LEN, (BQ + QB - 1) / QB);
    cfg.blockDim = dim3(K2_THREADS, 1, 1);
    cudaLaunchAttribute attrs[1];
    attrs[0].id = cudaLaunchAttributeProgrammaticStreamSerialization;
    attrs[0].val.programmaticStreamSerializationAllowed = 1;
    cfg.attrs = attrs;
    cfg.numAttrs = 1;
    cudaLaunchKernelEx(&cfg, expand_kernel, p, out, BQ);
}